// round 1
// baseline (speedup 1.0000x reference)
#include <cuda_runtime.h>
#include <stdint.h>

#define N_NODES 100000
#define DIM 256
#define NS 64
#define CANDN 160
#define TK 16
#define MODCAP 128

// -------- scratch (static device globals; no runtime allocation) --------
__device__ float g_D[(size_t)NS * N_NODES];   // D[s][j] = dot(x_s, V_j)  (25.6 MB)
__device__ float g_vn[N_NODES];               // ||V_j||^2
__device__ float g_G[NS * NS];                // G[i][t] = dot(x_i, x_t); diag = ||x||^2
__device__ unsigned long long g_cand[NS * CANDN]; // per sample: sorted (d2bits<<32)|idx

__device__ __forceinline__ unsigned long long u64min(unsigned long long a, unsigned long long b) { return a < b ? a : b; }
__device__ __forceinline__ unsigned long long u64max(unsigned long long a, unsigned long long b) { return a > b ? a : b; }

// ---------------- K1: Gram matrix G = X X^T ----------------
__global__ void k_gram(const float* __restrict__ X) {
    __shared__ float sx[DIM];
    __shared__ float red[256];
    int b = blockIdx.x, tid = threadIdx.x;
    sx[tid] = X[b * DIM + tid];
    __syncthreads();
    int j = tid & 63, q = tid >> 6;
    const float* xj = X + (size_t)j * DIM + q * 64;
    const float* xb = sx + q * 64;
    float p = 0.f;
#pragma unroll
    for (int k = 0; k < 64; ++k) p += xb[k] * xj[k];
    red[tid] = p;
    __syncthreads();
    if (tid < 64)
        g_G[b * NS + tid] = red[tid] + red[tid + 64] + red[tid + 128] + red[tid + 192];
}

// ---------------- K2: D = X V^T and vnorms (main cost) ----------------
// block: 64 nodes; threads 256 = 16 sample-groups x 16 node-groups; 4x4 register tile.
__global__ __launch_bounds__(256) void k_gemm(const float* __restrict__ X, const float* __restrict__ V) {
    __shared__ __align__(16) float sX[64][68];   // sX[k][s]
    __shared__ __align__(16) float sV[64][68];   // sV[k][j]
    int tid = threadIdx.x;
    int j0 = blockIdx.x * 64;
    int nvalid = N_NODES - j0; if (nvalid > 64) nvalid = 64;
    int sg = tid & 15, jg = tid >> 4;
    int r = tid >> 2, kq = tid & 3;
    bool vok = (r < nvalid);

    float acc[4][4];
#pragma unroll
    for (int a = 0; a < 4; ++a)
#pragma unroll
        for (int c = 0; c < 4; ++c) acc[a][c] = 0.f;
    float vnacc = 0.f;

    const float* Xp = X + (size_t)r * DIM + kq * 4;
    const float* Vp = V + (size_t)(vok ? (j0 + r) : 0) * DIM + kq * 4;

    for (int kc = 0; kc < DIM; kc += 64) {
#pragma unroll
        for (int u = 0; u < 4; ++u) {
            int k = kq * 4 + u * 16;
            float4 fx = *(const float4*)(Xp + kc + u * 16);
            sX[k + 0][r] = fx.x; sX[k + 1][r] = fx.y; sX[k + 2][r] = fx.z; sX[k + 3][r] = fx.w;
            float4 fv = vok ? *(const float4*)(Vp + kc + u * 16) : make_float4(0.f, 0.f, 0.f, 0.f);
            sV[k + 0][r] = fv.x; sV[k + 1][r] = fv.y; sV[k + 2][r] = fv.z; sV[k + 3][r] = fv.w;
            vnacc += fv.x * fv.x + fv.y * fv.y + fv.z * fv.z + fv.w * fv.w;
        }
        __syncthreads();
#pragma unroll 16
        for (int kk = 0; kk < 64; ++kk) {
            float4 xv = *(const float4*)&sX[kk][sg * 4];
            float4 vv = *(const float4*)&sV[kk][jg * 4];
            acc[0][0] += xv.x * vv.x; acc[0][1] += xv.x * vv.y; acc[0][2] += xv.x * vv.z; acc[0][3] += xv.x * vv.w;
            acc[1][0] += xv.y * vv.x; acc[1][1] += xv.y * vv.y; acc[1][2] += xv.y * vv.z; acc[1][3] += xv.y * vv.w;
            acc[2][0] += xv.z * vv.x; acc[2][1] += xv.z * vv.y; acc[2][2] += xv.z * vv.z; acc[2][3] += xv.z * vv.w;
            acc[3][0] += xv.w * vv.x; acc[3][1] += xv.w * vv.y; acc[3][2] += xv.w * vv.z; acc[3][3] += xv.w * vv.w;
        }
        __syncthreads();
    }

    // reduce vnorm across the 4 kq-threads of each row (adjacent lanes)
    vnacc += __shfl_down_sync(0xffffffffu, vnacc, 1);
    vnacc += __shfl_down_sync(0xffffffffu, vnacc, 2);
    if (kq == 0 && vok) g_vn[j0 + r] = vnacc;

    int jb = jg * 4;
    if (jb < nvalid) {
        bool full = (jb + 4 <= nvalid);
#pragma unroll
        for (int a = 0; a < 4; ++a) {
            int s = sg * 4 + a;
            float4 o = make_float4(acc[a][0], acc[a][1], acc[a][2], acc[a][3]);
            float* dst = g_D + (size_t)s * N_NODES + j0 + jb;
            if (full) {
                *(float4*)dst = o;
            } else {
                float ov[4] = {o.x, o.y, o.z, o.w};
                for (int c = 0; c < 4; ++c) if (jb + c < nvalid) dst[c] = ov[c];
            }
        }
    }
}

// ---------------- K3: per-sample top-CANDN baseline candidates ----------------
__global__ __launch_bounds__(256) void k_cand() {
    __shared__ unsigned long long keys[4096];
    int i = blockIdx.x, tid = threadIdx.x;
    float xn = g_G[i * NS + i];
    float lv[TK]; unsigned li[TK];
#pragma unroll
    for (int m = 0; m < TK; ++m) { lv[m] = 3.4e38f; li[m] = 0xffffffffu; }
    const float* Drow = g_D + (size_t)i * N_NODES;
    for (int j = tid; j < N_NODES; j += 256) {
        float d2 = xn - 2.f * __ldg(&Drow[j]) + __ldg(&g_vn[j]);
        if (d2 < lv[TK - 1]) {
            int pos = TK - 1;
            while (pos > 0 && lv[pos - 1] > d2) { lv[pos] = lv[pos - 1]; li[pos] = li[pos - 1]; --pos; }
            lv[pos] = d2; li[pos] = (unsigned)j;
        }
    }
#pragma unroll
    for (int m = 0; m < TK; ++m)
        keys[tid * TK + m] = ((unsigned long long)__float_as_uint(lv[m]) << 32) | li[m];
    __syncthreads();
    // bitonic sort ascending (d2, then idx)
    for (int k = 2; k <= 4096; k <<= 1) {
        for (int j2 = k >> 1; j2 > 0; j2 >>= 1) {
            for (int t = tid; t < 4096; t += 256) {
                int ixj = t ^ j2;
                if (ixj > t) {
                    unsigned long long a = keys[t], b = keys[ixj];
                    bool up = ((t & k) == 0);
                    if ((a > b) == up) { keys[t] = b; keys[ixj] = a; }
                }
            }
            __syncthreads();
        }
    }
    if (tid < CANDN) g_cand[i * CANDN + tid] = keys[tid];
}

// ---------------- K4: sequential 64-step BMU loop (single block) ----------------
__global__ __launch_bounds__(256) void k_seq(const int* __restrict__ itp, float* __restrict__ out) {
    __shared__ int   mod_idx[MODCAP];
    __shared__ float mod_vn[MODCAP];
    __shared__ float mod_D[MODCAP * 64];          // mod_D[m][t] = dot(x_t, V_node_m current)
    __shared__ unsigned bm[N_NODES / 32];         // modified-node bitmap (3125 words)
    __shared__ unsigned long long wred[16];
    __shared__ unsigned long long s_k1, s_k2;
    __shared__ int s_mb, s_ms, s_newb, s_news, s_nmod;

    int tid = threadIdx.x;
    for (int w = tid; w < N_NODES / 32; w += 256) bm[w] = 0;
    if (tid == 0) s_nmod = 0;
    int it = itp ? *itp : 0;
    float eb = 1.0f / (float)(it + 2);
    float en = 1.0f / (float)((it + 1) * 100);
    __syncthreads();

    unsigned long long kcur = (tid < CANDN) ? __ldg(&g_cand[tid]) : ~0ull;

    for (int i = 0; i < NS; ++i) {
        unsigned long long knext = (tid < CANDN && i + 1 < NS) ? __ldg(&g_cand[(i + 1) * CANDN + tid]) : ~0ull;
        float xn = g_G[i * NS + i];
        int nmod = s_nmod;

        unsigned long long k1 = ~0ull, k2 = ~0ull;
        if (tid < CANDN) {
            unsigned idx = (unsigned)kcur & 0xffffffffu;
            if (!((bm[idx >> 5] >> (idx & 31)) & 1u)) k1 = kcur;   // skip modified (covered below)
        }
        if (tid < nmod) {
            float d2 = xn - 2.f * mod_D[tid * 64 + i] + mod_vn[tid];
            unsigned long long key = ((unsigned long long)__float_as_uint(d2) << 32) | (unsigned)mod_idx[tid];
            if (key < k1) { k2 = k1; k1 = key; } else if (key < k2) k2 = key;
        }
        // warp-level top-2 reduction
#pragma unroll
        for (int off = 16; off; off >>= 1) {
            unsigned long long b1 = __shfl_down_sync(0xffffffffu, k1, off);
            unsigned long long b2 = __shfl_down_sync(0xffffffffu, k2, off);
            unsigned long long m1 = u64min(k1, b1);
            unsigned long long m2 = u64min(u64max(k1, b1), u64min(k2, b2));
            k1 = m1; k2 = m2;
        }
        if ((tid & 31) == 0) { wred[(tid >> 5) * 2] = k1; wred[(tid >> 5) * 2 + 1] = k2; }
        __syncthreads();
        if (tid == 0) {
            unsigned long long r1 = wred[0], r2 = wred[1];
            for (int w = 1; w < 8; ++w) {
                unsigned long long b1 = wred[w * 2], b2 = wred[w * 2 + 1];
                unsigned long long m1 = u64min(r1, b1);
                r2 = u64min(u64max(r1, b1), u64min(r2, b2));
                r1 = m1;
            }
            s_k1 = r1; s_k2 = r2;
            out[2 * i]     = sqrtf(__uint_as_float((unsigned)(r1 >> 32)) + 1e-12f);
            out[2 * i + 1] = sqrtf(__uint_as_float((unsigned)(r2 >> 32)) + 1e-12f);
            s_mb = -1; s_ms = -1;
        }
        __syncthreads();
        int nb  = (int)(s_k1 & 0xffffffffu);
        int nsd = (int)(s_k2 & 0xffffffffu);
        // locate in mod table (parallel)
        if (tid < nmod) {
            int mi = mod_idx[tid];
            if (mi == nb)  s_mb = tid;
            if (mi == nsd) s_ms = tid;
        }
        __syncthreads();
        if (tid == 0) {
            if (s_mb < 0) { s_mb = s_nmod++; mod_idx[s_mb] = nb;  bm[nb >> 5]  |= 1u << (nb & 31);  s_newb = 1; } else s_newb = 0;
            if (s_ms < 0) { s_ms = s_nmod++; mod_idx[s_ms] = nsd; bm[nsd >> 5] |= 1u << (nsd & 31); s_news = 1; } else s_news = 0;
        }
        __syncthreads();
        int mb = s_mb, ms = s_ms;
        // gather baseline rows for newly-touched nodes (parallel for b and s)
        if (s_newb) {
            if (tid < 64) mod_D[mb * 64 + tid] = g_D[(size_t)tid * N_NODES + nb];
            if (tid == 64) mod_vn[mb] = g_vn[nb];
        }
        if (s_news) {
            if (tid >= 128 && tid < 192) mod_D[ms * 64 + (tid - 128)] = g_D[(size_t)(tid - 128) * N_NODES + nsd];
            if (tid == 192) mod_vn[ms] = g_vn[nsd];
        }
        __syncthreads();
        // norm recurrences (must read OLD dot) ...
        if (tid == 0) {
            float dold = mod_D[mb * 64 + i];
            float om = 1.f - eb;
            mod_vn[mb] = om * om * mod_vn[mb] + 2.f * eb * om * dold + eb * eb * xn;
        }
        if (tid == 1) {
            float dold = mod_D[ms * 64 + i];
            float om = 1.f - en;
            mod_vn[ms] = om * om * mod_vn[ms] + 2.f * en * om * dold + en * en * xn;
        }
        __syncthreads();
        // ... then dot recurrences
        if (tid < 64) {
            mod_D[mb * 64 + tid] = (1.f - eb) * mod_D[mb * 64 + tid] + eb * g_G[i * NS + tid];
        } else if (tid < 128) {
            int t = tid - 64;
            mod_D[ms * 64 + t] = (1.f - en) * mod_D[ms * 64 + t] + en * g_G[i * NS + t];
        }
        __syncthreads();
        kcur = knext;
    }
}

extern "C" void kernel_launch(void* const* d_in, const int* in_sizes, int n_in,
                              void* d_out, int out_size) {
    const float* X = (const float*)d_in[0];       // data [64,256]
    const float* V = (const float*)d_in[1];       // V [100000,256]
    const int* itp = (n_in > 3) ? (const int*)d_in[3] : nullptr;  // it scalar
    float* out = (float*)d_out;                   // [64,2]

    k_gram<<<NS, 256>>>(X);
    k_gemm<<<(N_NODES + 63) / 64, 256>>>(X, V);
    k_cand<<<NS, 256>>>();
    k_seq<<<1, 256>>>(itp, out);
}